// round 2
// baseline (speedup 1.0000x reference)
#include <cuda_runtime.h>
#include <math.h>

#define Hc 128
#define Wc 128
#define HWc 16384

// Scratch (static device globals are allowed; runtime allocation is not)
__device__ float g_x1[2*64*HWc];   // post-PReLU conv1 output
__device__ float g_f [2*32*HWc];   // post-ReLU reduce output
__device__ float g_zp[2*2*HWc];    // ZPool: [max, mean] over f channels
__device__ float g_x2[2*64*HWc];   // post-PReLU involution output
__device__ float g_h [2*32*HWc];   // post-PReLU psec 3x3 output

// ---------------------------------------------------------------------------
// K1: x -> x1 = prelu(W1 x + b1), f = relu(Wr x1 + br), zp = [max_c f, mean_c f]
// One block = 64 consecutive pixels of a row. 256 threads.
// ---------------------------------------------------------------------------
__global__ __launch_bounds__(256) void k_front(
    const float* __restrict__ x,  const float* __restrict__ w1,
    const float* __restrict__ b1, const float* __restrict__ a1p,
    const float* __restrict__ wr, const float* __restrict__ br)
{
  extern __shared__ float sm[];
  float* xs  = sm;              // 64*129
  float* w1s = xs + 64*129;     // 8192
  float* x1s = w1s + 8192;      // 64*65
  float* wrs = x1s + 64*65;     // 2048
  float* fs  = wrs + 2048;      // 64*33
  const int t = threadIdx.x;
  const int tile = blockIdx.x;            // 0..511
  const int w0 = (tile & 1) << 6;
  const int h  = (tile >> 1) & (Hc - 1);
  const int b  = tile >> 8;
  const float a1 = *a1p;

  const float* xbase = x + (b*128)*HWc + h*Wc + w0;
  for (int i = t; i < 64*128; i += 256) {
    int c = i >> 6, p = i & 63;
    xs[p*129 + c] = xbase[c*HWc + p];
  }
  for (int i = t; i < 8192; i += 256) w1s[i] = w1[i];
  for (int i = t; i < 2048; i += 256) wrs[i] = wr[i];
  __syncthreads();

  const int p = t & 63, g = t >> 6;       // g in 0..3

  // x1: 16 output channels per thread
  {
    const int ocb = g*16;
    float acc[16];
    #pragma unroll
    for (int o = 0; o < 16; o++) acc[o] = b1[ocb + o];
    #pragma unroll 4
    for (int c = 0; c < 128; c++) {
      float xv = xs[p*129 + c];
      #pragma unroll
      for (int o = 0; o < 16; o++) acc[o] += w1s[(ocb + o)*128 + c] * xv;
    }
    #pragma unroll
    for (int o = 0; o < 16; o++) {
      float v = acc[o];
      x1s[p*65 + ocb + o] = (v >= 0.f) ? v : a1 * v;
    }
  }
  __syncthreads();

  float* gx1b = g_x1 + (b*64)*HWc + h*Wc + w0;
  for (int i = t; i < 4096; i += 256) {
    int c = i >> 6, pp = i & 63;
    gx1b[c*HWc + pp] = x1s[pp*65 + c];
  }

  // f: 8 output channels per thread
  {
    const int fb = g*8;
    float acc[8];
    #pragma unroll
    for (int o = 0; o < 8; o++) acc[o] = br[fb + o];
    #pragma unroll 4
    for (int c = 0; c < 64; c++) {
      float xv = x1s[p*65 + c];
      #pragma unroll
      for (int o = 0; o < 8; o++) acc[o] += wrs[(fb + o)*64 + c] * xv;
    }
    #pragma unroll
    for (int o = 0; o < 8; o++)
      fs[p*33 + fb + o] = fmaxf(acc[o], 0.f);
  }
  __syncthreads();

  float* gfb = g_f + (b*32)*HWc + h*Wc + w0;
  for (int i = t; i < 2048; i += 256) {
    int c = i >> 6, pp = i & 63;
    gfb[c*HWc + pp] = fs[pp*33 + c];
  }
  if (t < 64) {
    float mx = -1e30f, sum = 0.f;
    #pragma unroll
    for (int c = 0; c < 32; c++) {
      float v = fs[t*33 + c];
      mx = fmaxf(mx, v);
      sum += v;
    }
    float* z = g_zp + (b*2)*HWc + h*Wc + w0 + t;
    z[0]   = mx;
    z[HWc] = sum * (1.f/32.f);
  }
}

// ---------------------------------------------------------------------------
// K2: involution. Per pixel: kw[g][49] = Ws f + bs; x2[c] = sum_t kw * x1_patch.
// Tile 8x8, halo 14x14 of x1 in smem. 256 threads = 64 px * 4 groups.
// Stores prelu(x2, a2).
// ---------------------------------------------------------------------------
__global__ __launch_bounds__(256, 2) void k_inv(
    const float* __restrict__ ws, const float* __restrict__ bs,
    const float* __restrict__ a2p)
{
  extern __shared__ float sm[];
  float* x1h = sm;                // 64*196 = 12544
  float* wss = x1h + 12544;       // 6272
  float* bss = wss + 6272;        // 196
  float* fts = bss + 196;         // 64*33 = 2112
  const int t = threadIdx.x;
  const int w0 = blockIdx.x << 3;
  const int h0 = blockIdx.y << 3;
  const int b  = blockIdx.z;
  const float a2 = *a2p;

  const float* gx1b = g_x1 + (b*64)*HWc;
  for (int i = t; i < 12544; i += 256) {
    int c = i / 196;
    int r = i - c*196;
    int yy = r / 14, xx = r - yy*14;
    int gh = h0 - 3 + yy, gw = w0 - 3 + xx;
    float v = 0.f;
    if ((unsigned)gh < 128u && (unsigned)gw < 128u)
      v = gx1b[c*HWc + gh*Wc + gw];
    x1h[i] = v;
  }
  for (int i = t; i < 6272; i += 256) wss[i] = ws[i];
  if (t < 196) bss[t] = bs[t];
  const float* gfb = g_f + (b*32)*HWc;
  for (int i = t; i < 2048; i += 256) {
    int c = i >> 6, p = i & 63;
    fts[p*33 + c] = gfb[c*HWc + (h0 + (p >> 3))*Wc + w0 + (p & 7)];
  }
  __syncthreads();

  const int p = t & 63, j = t >> 6;
  const int px = p & 7, py = p >> 3;

  float fv[32];
  #pragma unroll
  for (int c = 0; c < 32; c++) fv[c] = fts[p*33 + c];

  float acc[16];
  #pragma unroll
  for (int ch = 0; ch < 16; ch++) acc[ch] = 0.f;

  const float* wbase = wss + j*49*32;
  const float* bbase = bss + j*49;
  const float* xbase = x1h + (j*16)*196 + py*14 + px;

  for (int dy = 0; dy < 7; dy++) {
    for (int dx = 0; dx < 7; dx++) {
      const int tt = dy*7 + dx;
      float kwt = bbase[tt];
      const float* wrow = wbase + tt*32;
      #pragma unroll
      for (int c = 0; c < 32; c++) kwt += wrow[c] * fv[c];
      const float* src = xbase + dy*14 + dx;
      #pragma unroll
      for (int ch = 0; ch < 16; ch++)
        acc[ch] += kwt * src[ch*196];
    }
  }

  float* gx2b = g_x2 + (b*64 + j*16)*HWc + (h0 + py)*Wc + (w0 + px);
  #pragma unroll
  for (int ch = 0; ch < 16; ch++) {
    float v = acc[ch];
    gx2b[ch*HWc] = (v >= 0.f) ? v : a2 * v;
  }
}

// ---------------------------------------------------------------------------
// K3: psec 3x3 conv: h = prelu(conv3x3(f, wp1) + bp1, ap).
// Tile 16x16, halo 18x18 of f in smem. 1 thread/pixel, 32 out channels.
// ---------------------------------------------------------------------------
__global__ __launch_bounds__(256, 2) void k_psec1(
    const float* __restrict__ wp1, const float* __restrict__ bp1,
    const float* __restrict__ app)
{
  extern __shared__ float sm[];
  float* fh  = sm;            // 32*324 = 10368
  float* wps = fh + 10368;    // 9216
  const int t = threadIdx.x;
  const int w0 = blockIdx.x << 4;
  const int h0 = blockIdx.y << 4;
  const int b  = blockIdx.z;
  const float ap = *app;

  const float* gfb = g_f + (b*32)*HWc;
  for (int i = t; i < 10368; i += 256) {
    int c = i / 324;
    int r = i - c*324;
    int yy = r / 18, xx = r - yy*18;
    int gh = h0 - 1 + yy, gw = w0 - 1 + xx;
    float v = 0.f;
    if ((unsigned)gh < 128u && (unsigned)gw < 128u)
      v = gfb[c*HWc + gh*Wc + gw];
    fh[i] = v;
  }
  for (int i = t; i < 9216; i += 256) wps[i] = wp1[i];
  __syncthreads();

  const int px = t & 15, py = t >> 4;
  float acc[32];
  #pragma unroll
  for (int o = 0; o < 32; o++) acc[o] = bp1[o];

  for (int ci = 0; ci < 32; ci++) {
    #pragma unroll
    for (int tap = 0; tap < 9; tap++) {
      const int di = tap / 3, dj = tap - di*3;
      float xv = fh[ci*324 + (py + di)*18 + (px + dj)];
      #pragma unroll
      for (int o = 0; o < 32; o++)
        acc[o] += wps[(o*32 + ci)*9 + tap] * xv;
    }
  }

  float* ghb = g_h + (b*32)*HWc + (h0 + py)*Wc + (w0 + px);
  #pragma unroll
  for (int o = 0; o < 32; o++) {
    float v = acc[o];
    ghb[o*HWc] = (v >= 0.f) ? v : ap * v;
  }
}

// ---------------------------------------------------------------------------
// K4: x3 = W2 x2 + b2; attn = sigmoid(conv7x7(zp)); ps = Wp2 h + bp2;
//     out = x3*attn + ps. Tile 8x8, 4 threads/px (32 oc each).
// ---------------------------------------------------------------------------
__global__ __launch_bounds__(256, 2) void k_final(
    const float* __restrict__ w2,  const float* __restrict__ b2,
    const float* __restrict__ wa,  const float* __restrict__ ba,
    const float* __restrict__ wp2, const float* __restrict__ bp2,
    float* __restrict__ out)
{
  extern __shared__ float sm[];
  float* x2t = sm;            // 64*65 = 4160
  float* ht  = x2t + 4160;    // 64*33 = 2112
  float* zph = ht + 2112;     // 2*196 = 392
  float* w2s = zph + 392;     // 8192
  float* wps = w2s + 8192;    // 4096
  float* was = wps + 4096;    // 98
  const int t = threadIdx.x;
  const int w0 = blockIdx.x << 3;
  const int h0 = blockIdx.y << 3;
  const int b  = blockIdx.z;

  const float* gx2b = g_x2 + (b*64)*HWc;
  for (int i = t; i < 4096; i += 256) {
    int c = i >> 6, p = i & 63;
    x2t[p*65 + c] = gx2b[c*HWc + (h0 + (p >> 3))*Wc + w0 + (p & 7)];
  }
  const float* ghb = g_h + (b*32)*HWc;
  for (int i = t; i < 2048; i += 256) {
    int c = i >> 6, p = i & 63;
    ht[p*33 + c] = ghb[c*HWc + (h0 + (p >> 3))*Wc + w0 + (p & 7)];
  }
  const float* gzb = g_zp + (b*2)*HWc;
  for (int i = t; i < 392; i += 256) {
    int c = i / 196;
    int r = i - c*196;
    int yy = r / 14, xx = r - yy*14;
    int gh = h0 - 3 + yy, gw = w0 - 3 + xx;
    float v = 0.f;
    if ((unsigned)gh < 128u && (unsigned)gw < 128u)
      v = gzb[c*HWc + gh*Wc + gw];
    zph[i] = v;
  }
  for (int i = t; i < 8192; i += 256) w2s[i] = w2[i];
  for (int i = t; i < 4096; i += 256) wps[i] = wp2[i];
  if (t < 98) was[t] = wa[t];
  __syncthreads();

  const int p = t & 63, j = t >> 6;
  const int px = p & 7, py = p >> 3;

  // attention (computed redundantly by the 4 threads of a pixel; it's 98 FMA)
  float aacc = *ba;
  #pragma unroll
  for (int dy = 0; dy < 7; dy++)
    #pragma unroll
    for (int dx = 0; dx < 7; dx++) {
      const int off = (py + dy)*14 + px + dx;
      aacc += was[dy*7 + dx] * zph[off] + was[49 + dy*7 + dx] * zph[196 + off];
    }
  const float attn = 1.f / (1.f + expf(-aacc));

  const int ocb = j*32;
  float acc[32];
  #pragma unroll
  for (int o = 0; o < 32; o++) acc[o] = b2[ocb + o];
  #pragma unroll 4
  for (int c = 0; c < 64; c++) {
    float xv = x2t[p*65 + c];
    #pragma unroll
    for (int o = 0; o < 32; o++) acc[o] += w2s[(ocb + o)*64 + c] * xv;
  }
  #pragma unroll
  for (int o = 0; o < 32; o++) acc[o] = acc[o]*attn + bp2[ocb + o];
  #pragma unroll 4
  for (int c = 0; c < 32; c++) {
    float hv = ht[p*33 + c];
    #pragma unroll
    for (int o = 0; o < 32; o++) acc[o] += wps[(ocb + o)*32 + c] * hv;
  }

  float* ob = out + (b*128)*HWc + (h0 + py)*Wc + (w0 + px);
  #pragma unroll
  for (int o = 0; o < 32; o++) ob[(ocb + o)*HWc] = acc[o];
}

// ---------------------------------------------------------------------------
extern "C" void kernel_launch(void* const* d_in, const int* in_sizes, int n_in,
                              void* d_out, int out_size)
{
  const float* x   = (const float*)d_in[0];
  const float* w1  = (const float*)d_in[1];
  const float* b1  = (const float*)d_in[2];
  const float* a1  = (const float*)d_in[3];
  const float* wr  = (const float*)d_in[4];
  const float* br  = (const float*)d_in[5];
  const float* ws  = (const float*)d_in[6];
  const float* bs  = (const float*)d_in[7];
  const float* a2  = (const float*)d_in[8];
  const float* w2  = (const float*)d_in[9];
  const float* b2  = (const float*)d_in[10];
  const float* wa  = (const float*)d_in[11];
  const float* ba  = (const float*)d_in[12];
  const float* wp1 = (const float*)d_in[13];
  const float* bp1 = (const float*)d_in[14];
  const float* ap  = (const float*)d_in[15];
  const float* wp2 = (const float*)d_in[16];
  const float* bp2 = (const float*)d_in[17];
  float* out = (float*)d_out;

  const int s1 = 24768 * 4;   // k_front smem bytes
  const int s2 = 21124 * 4;   // k_inv
  const int s3 = 19584 * 4;   // k_psec1
  const int s4 = 19050 * 4;   // k_final

  cudaFuncSetAttribute(k_front, cudaFuncAttributeMaxDynamicSharedMemorySize, s1);
  cudaFuncSetAttribute(k_inv,   cudaFuncAttributeMaxDynamicSharedMemorySize, s2);
  cudaFuncSetAttribute(k_psec1, cudaFuncAttributeMaxDynamicSharedMemorySize, s3);
  cudaFuncSetAttribute(k_final, cudaFuncAttributeMaxDynamicSharedMemorySize, s4);

  k_front<<<512, 256, s1>>>(x, w1, b1, a1, wr, br);
  k_inv  <<<dim3(16, 16, 2), 256, s2>>>(ws, bs, a2);
  k_psec1<<<dim3(8, 8, 2),   256, s3>>>(wp1, bp1, ap);
  k_final<<<dim3(16, 16, 2), 256, s4>>>(w2, b2, wa, ba, wp2, bp2, out);
}

// round 3
// speedup vs baseline: 1.2717x; 1.2717x over previous
#include <cuda_runtime.h>
#include <math.h>

#define Hc 128
#define Wc 128
#define HWc 16384

// Scratch (static device globals; runtime allocation forbidden)
__device__ float g_x1[2*64*HWc];   // post-PReLU conv1 output
__device__ float g_f [2*32*HWc];   // post-ReLU reduce output
__device__ float g_zp[2*2*HWc];    // ZPool: [max, mean] over f channels
__device__ float g_x2[2*64*HWc];   // post-PReLU involution output
__device__ float g_h [2*32*HWc];   // post-PReLU psec 3x3 output

// ---------------------------------------------------------------------------
// K1: one row (128 px). conv1 (128->64) + PReLU -> x1 ; reduce (64->32)+ReLU -> f ;
// ZPool -> zp. Register tiles: conv1 4oc x 8px, reduce 4oc x 4px.
// ---------------------------------------------------------------------------
__global__ __launch_bounds__(256, 2) void k_front(
    const float* __restrict__ x,  const float* __restrict__ w1,
    const float* __restrict__ b1, const float* __restrict__ a1p,
    const float* __restrict__ wr, const float* __restrict__ br)
{
  extern __shared__ float sm[];
  float* xs  = sm;              // 32*132 = 4224 (chunked input)
  float* w1t = xs + 4224;       // 8192  [c][oc]
  float* x1s = w1t + 8192;      // 64*132 = 8448
  float* wrt = x1s + 8448;      // 2048  [c][oc]
  float* fs  = wrt + 2048;      // 32*132 = 4224
  const int t = threadIdx.x;
  const int h = blockIdx.x & 127;
  const int b = blockIdx.x >> 7;
  const float a1 = *a1p;

  for (int i = t; i < 8192; i += 256) { int c = i >> 6, oc = i & 63; w1t[i] = w1[oc*128 + c]; }
  for (int i = t; i < 2048; i += 256) { int c = i >> 5, oc = i & 31; wrt[i] = wr[oc*64 + c]; }

  const int oc0 = (t >> 4) * 4;     // 16 oc-groups x 4
  const int px0 = (t & 15) * 8;     // 16 px-groups x 8
  float acc[4][8];
  #pragma unroll
  for (int o = 0; o < 4; o++) {
    float bv = b1[oc0 + o];
    #pragma unroll
    for (int p = 0; p < 8; p++) acc[o][p] = bv;
  }

  const float* xb = x + (b*128)*HWc + h*Wc;
  for (int cc = 0; cc < 4; cc++) {
    __syncthreads();
    for (int i = t; i < 4096; i += 256) {
      int ci = i >> 7, p = i & 127;
      xs[ci*132 + p] = xb[(cc*32 + ci)*HWc + p];
    }
    __syncthreads();
    #pragma unroll 4
    for (int ci = 0; ci < 32; ci++) {
      const int c = cc*32 + ci;
      float4 wv  = *(const float4*)&w1t[c*64 + oc0];
      float4 xa  = *(const float4*)&xs[ci*132 + px0];
      float4 xb4 = *(const float4*)&xs[ci*132 + px0 + 4];
      float xv[8] = {xa.x,xa.y,xa.z,xa.w,xb4.x,xb4.y,xb4.z,xb4.w};
      float wvv[4] = {wv.x,wv.y,wv.z,wv.w};
      #pragma unroll
      for (int o = 0; o < 4; o++)
        #pragma unroll
        for (int p = 0; p < 8; p++)
          acc[o][p] += wvv[o]*xv[p];
    }
  }

  float* gx1b = g_x1 + (b*64)*HWc + h*Wc;
  #pragma unroll
  for (int o = 0; o < 4; o++) {
    float v4[8];
    #pragma unroll
    for (int p = 0; p < 8; p++) { float v = acc[o][p]; v4[p] = (v >= 0.f) ? v : a1*v; }
    *(float4*)&x1s[(oc0+o)*132 + px0]     = make_float4(v4[0],v4[1],v4[2],v4[3]);
    *(float4*)&x1s[(oc0+o)*132 + px0 + 4] = make_float4(v4[4],v4[5],v4[6],v4[7]);
    *(float4*)&gx1b[(oc0+o)*HWc + px0]     = make_float4(v4[0],v4[1],v4[2],v4[3]);
    *(float4*)&gx1b[(oc0+o)*HWc + px0 + 4] = make_float4(v4[4],v4[5],v4[6],v4[7]);
  }
  __syncthreads();

  // reduce: 32 oc x 128 px
  const int ocr = (t >> 5) * 4;     // 8 groups x 4
  const int pxr = (t & 31) * 4;     // 32 groups x 4
  float racc[4][4];
  #pragma unroll
  for (int o = 0; o < 4; o++) {
    float bv = br[ocr + o];
    #pragma unroll
    for (int p = 0; p < 4; p++) racc[o][p] = bv;
  }
  #pragma unroll 4
  for (int c = 0; c < 64; c++) {
    float4 wv = *(const float4*)&wrt[c*32 + ocr];
    float4 xv = *(const float4*)&x1s[c*132 + pxr];
    float wvv[4] = {wv.x,wv.y,wv.z,wv.w};
    float xvv[4] = {xv.x,xv.y,xv.z,xv.w};
    #pragma unroll
    for (int o = 0; o < 4; o++)
      #pragma unroll
      for (int p = 0; p < 4; p++)
        racc[o][p] += wvv[o]*xvv[p];
  }
  float* gfb = g_f + (b*32)*HWc + h*Wc;
  #pragma unroll
  for (int o = 0; o < 4; o++) {
    float v4[4];
    #pragma unroll
    for (int p = 0; p < 4; p++) v4[p] = fmaxf(racc[o][p], 0.f);
    *(float4*)&fs[(ocr+o)*132 + pxr] = make_float4(v4[0],v4[1],v4[2],v4[3]);
    *(float4*)&gfb[(ocr+o)*HWc + pxr] = make_float4(v4[0],v4[1],v4[2],v4[3]);
  }
  __syncthreads();

  if (t < 128) {
    float mx = -1e30f, sum = 0.f;
    #pragma unroll
    for (int c = 0; c < 32; c++) {
      float v = fs[c*132 + t];
      mx = fmaxf(mx, v);
      sum += v;
    }
    g_zp[(b*2)*HWc + h*Wc + t]   = mx;
    g_zp[(b*2+1)*HWc + h*Wc + t] = sum * (1.f/32.f);
  }
}

// ---------------------------------------------------------------------------
// K2: involution. Tile 32x2 px (warp lanes along x -> conflict-free halo reads).
// 256 thr = 4 groups x 64 px. Span kernels computed with fv in regs + float4
// broadcast weight loads; kwt uses 4 partial accumulators.
// ---------------------------------------------------------------------------
__global__ __launch_bounds__(256, 2) void k_inv(
    const float* __restrict__ ws, const float* __restrict__ bs,
    const float* __restrict__ a2p)
{
  extern __shared__ float sm[];
  float* x1h = sm;                // 64ch * 8row * 38col = 19456
  float* wss = x1h + 19456;       // 6272
  float* bss = wss + 6272;        // 196
  float* fts = bss + 196;         // 64*33 = 2112
  const int t = threadIdx.x;
  const int w0 = blockIdx.x << 5;   // tile 32 wide
  const int h0 = blockIdx.y << 1;   // tile 2 tall
  const int b  = blockIdx.z;
  const float a2 = *a2p;

  const float* gx1b = g_x1 + (b*64)*HWc;
  for (int i = t; i < 19456; i += 256) {
    int ch = i / 304, r = i - ch*304;
    int yy = r / 38, xx = r - yy*38;
    int gh = h0 - 3 + yy, gw = w0 - 3 + xx;
    float v = 0.f;
    if ((unsigned)gh < 128u && (unsigned)gw < 128u)
      v = gx1b[ch*HWc + gh*Wc + gw];
    x1h[i] = v;
  }
  for (int i = t; i < 6272; i += 256) wss[i] = ws[i];
  if (t < 196) bss[t] = bs[t];
  const float* gfb = g_f + (b*32)*HWc;
  for (int i = t; i < 2048; i += 256) {
    int c = i >> 6, p = i & 63;
    fts[p*33 + c] = gfb[c*HWc + (h0 + (p>>5))*Wc + w0 + (p&31)];
  }
  __syncthreads();

  const int p = t & 63, j = t >> 6;
  const int py = p >> 5, px = p & 31;

  float fv[32];
  #pragma unroll
  for (int c = 0; c < 32; c++) fv[c] = fts[p*33 + c];

  float acc[16];
  #pragma unroll
  for (int ch = 0; ch < 16; ch++) acc[ch] = 0.f;

  const float* wb = wss + j*49*32;
  const float* bb = bss + j*49;
  const float* xb = x1h + (j*16)*304 + py*38 + px;

  #pragma unroll 1
  for (int dy = 0; dy < 7; dy++) {
    #pragma unroll 1
    for (int dx = 0; dx < 7; dx++) {
      const int tt = dy*7 + dx;
      const float* wr2 = wb + tt*32;
      float k0 = 0.f, k1 = 0.f, k2 = 0.f, k3 = 0.f;
      #pragma unroll
      for (int c4 = 0; c4 < 8; c4++) {
        float4 wv = *(const float4*)&wr2[c4*4];
        k0 += wv.x*fv[c4*4+0];
        k1 += wv.y*fv[c4*4+1];
        k2 += wv.z*fv[c4*4+2];
        k3 += wv.w*fv[c4*4+3];
      }
      const float kwt = bb[tt] + (k0 + k1) + (k2 + k3);
      const float* src = xb + dy*38 + dx;
      #pragma unroll
      for (int ch = 0; ch < 16; ch++)
        acc[ch] += kwt * src[ch*304];
    }
  }

  float* gx2b = g_x2 + (b*64 + j*16)*HWc + (h0 + py)*Wc + (w0 + px);
  #pragma unroll
  for (int ch = 0; ch < 16; ch++) {
    float v = acc[ch];
    gx2b[ch*HWc] = (v >= 0.f) ? v : a2*v;
  }
}

// ---------------------------------------------------------------------------
// K3: psec 3x3 conv (32->32) + PReLU. Tile 16x16. Thread = 8oc x 4px.
// Weights transposed [ci][tap][oc] for broadcast float4 loads.
// ---------------------------------------------------------------------------
__global__ __launch_bounds__(256, 2) void k_psec1(
    const float* __restrict__ wp1, const float* __restrict__ bp1,
    const float* __restrict__ app)
{
  extern __shared__ float sm[];
  float* fh  = sm;            // 32*324 = 10368
  float* wpt = fh + 10368;    // 9216 [ci*9+tap][oc]
  const int t = threadIdx.x;
  const int w0 = blockIdx.x << 4;
  const int h0 = blockIdx.y << 4;
  const int b  = blockIdx.z;
  const float ap = *app;

  const float* gfb = g_f + (b*32)*HWc;
  for (int i = t; i < 10368; i += 256) {
    int c = i / 324, r = i - c*324;
    int yy = r / 18, xx = r - yy*18;
    int gh = h0 - 1 + yy, gw = w0 - 1 + xx;
    float v = 0.f;
    if ((unsigned)gh < 128u && (unsigned)gw < 128u)
      v = gfb[c*HWc + gh*Wc + gw];
    fh[i] = v;
  }
  for (int i = t; i < 9216; i += 256) {
    int tc = i >> 5, o = i & 31;
    wpt[i] = wp1[o*288 + tc];
  }
  __syncthreads();

  const int oc0 = (t >> 6) * 8;       // 4 groups x 8 oc
  const int pg  = t & 63;
  const int py  = pg >> 2, px0 = (pg & 3) * 4;

  float acc[8][4];
  #pragma unroll
  for (int o = 0; o < 8; o++) {
    float bv = bp1[oc0 + o];
    #pragma unroll
    for (int p = 0; p < 4; p++) acc[o][p] = bv;
  }

  #pragma unroll 1
  for (int ci = 0; ci < 32; ci++) {
    #pragma unroll
    for (int tap = 0; tap < 9; tap++) {
      const int di = tap / 3, dj = tap - di*3;
      float4 wa4 = *(const float4*)&wpt[(ci*9 + tap)*32 + oc0];
      float4 wb4 = *(const float4*)&wpt[(ci*9 + tap)*32 + oc0 + 4];
      const float* fr = &fh[ci*324 + (py + di)*18 + px0 + dj];
      float xv[4] = {fr[0], fr[1], fr[2], fr[3]};
      float wvv[8] = {wa4.x,wa4.y,wa4.z,wa4.w,wb4.x,wb4.y,wb4.z,wb4.w};
      #pragma unroll
      for (int o = 0; o < 8; o++)
        #pragma unroll
        for (int p = 0; p < 4; p++)
          acc[o][p] += wvv[o]*xv[p];
    }
  }

  float* ghb = g_h + (b*32)*HWc + (h0 + py)*Wc + (w0 + px0);
  #pragma unroll
  for (int o = 0; o < 8; o++) {
    float v4[4];
    #pragma unroll
    for (int p = 0; p < 4; p++) { float v = acc[o][p]; v4[p] = (v >= 0.f) ? v : ap*v; }
    *(float4*)&ghb[(oc0+o)*HWc] = make_float4(v4[0],v4[1],v4[2],v4[3]);
  }
}

// ---------------------------------------------------------------------------
// K4: one row (128 px), 128 oc. Thread = 8oc x 8px (64 acc).
// attn computed once per pixel into smem; conv2 + gate + psec 1x1 fused.
// ---------------------------------------------------------------------------
__global__ __launch_bounds__(256, 2) void k_final(
    const float* __restrict__ w2,  const float* __restrict__ b2,
    const float* __restrict__ wa,  const float* __restrict__ ba,
    const float* __restrict__ wp2, const float* __restrict__ bp2,
    float* __restrict__ out)
{
  extern __shared__ float sm[];
  float* x2t   = sm;             // 64*132 = 8448
  float* ht    = x2t + 8448;     // 32*132 = 4224
  float* w2t   = ht + 4224;      // 8192 [c][oc]
  float* wpt   = w2t + 8192;     // 4096 [c][oc]
  float* zph   = wpt + 4096;     // 2*7*136 = 1904
  float* was   = zph + 1904;     // 98
  float* attns = was + 98;       // 128
  const int t = threadIdx.x;
  const int h = blockIdx.x & 127;
  const int b = blockIdx.x >> 7;

  const float* gx2b = g_x2 + (b*64)*HWc + h*Wc;
  for (int i = t; i < 8192; i += 256) { int c = i >> 7, p = i & 127; x2t[c*132 + p] = gx2b[c*HWc + p]; }
  const float* ghb = g_h + (b*32)*HWc + h*Wc;
  for (int i = t; i < 4096; i += 256) { int c = i >> 7, p = i & 127; ht[c*132 + p] = ghb[c*HWc + p]; }
  for (int i = t; i < 8192; i += 256) { int c = i >> 7, oc = i & 127; w2t[i] = w2[oc*64 + c]; }
  for (int i = t; i < 4096; i += 256) { int c = i >> 7, oc = i & 127; wpt[i] = wp2[oc*32 + c]; }
  const float* gzb = g_zp + (b*2)*HWc;
  for (int i = t; i < 1904; i += 256) {
    int c = i / 952, r = i - c*952;
    int yy = r / 136, xx = r - yy*136;
    int gh = h - 3 + yy, gw = xx - 3;
    float v = 0.f;
    if ((unsigned)gh < 128u && (unsigned)gw < 128u)
      v = gzb[c*HWc + gh*Wc + gw];
    zph[i] = v;
  }
  if (t < 98) was[t] = wa[t];
  __syncthreads();

  if (t < 128) {
    float aacc = *ba;
    #pragma unroll
    for (int dy = 0; dy < 7; dy++)
      #pragma unroll
      for (int dx = 0; dx < 7; dx++) {
        const int o1 = dy*136 + t + dx;
        aacc += was[dy*7+dx]*zph[o1] + was[49 + dy*7+dx]*zph[952 + o1];
      }
    attns[t] = 1.f / (1.f + expf(-aacc));
  }
  __syncthreads();

  const int oc0 = (t >> 4) * 8;     // 16 groups x 8 oc
  const int px0 = (t & 15) * 8;     // 16 groups x 8 px
  float acc[8][8];
  #pragma unroll
  for (int o = 0; o < 8; o++) {
    float bv = b2[oc0 + o];
    #pragma unroll
    for (int p = 0; p < 8; p++) acc[o][p] = bv;
  }

  #pragma unroll 2
  for (int c = 0; c < 64; c++) {
    float4 wva = *(const float4*)&w2t[c*128 + oc0];
    float4 wvb = *(const float4*)&w2t[c*128 + oc0 + 4];
    float4 xa  = *(const float4*)&x2t[c*132 + px0];
    float4 xb4 = *(const float4*)&x2t[c*132 + px0 + 4];
    float wvv[8] = {wva.x,wva.y,wva.z,wva.w,wvb.x,wvb.y,wvb.z,wvb.w};
    float xvv[8] = {xa.x,xa.y,xa.z,xa.w,xb4.x,xb4.y,xb4.z,xb4.w};
    #pragma unroll
    for (int o = 0; o < 8; o++)
      #pragma unroll
      for (int p = 0; p < 8; p++)
        acc[o][p] += wvv[o]*xvv[p];
  }

  float av[8];
  #pragma unroll
  for (int p = 0; p < 8; p++) av[p] = attns[px0 + p];
  #pragma unroll
  for (int o = 0; o < 8; o++) {
    float bpv = bp2[oc0 + o];
    #pragma unroll
    for (int p = 0; p < 8; p++) acc[o][p] = acc[o][p]*av[p] + bpv;
  }

  #pragma unroll 2
  for (int c = 0; c < 32; c++) {
    float4 wva = *(const float4*)&wpt[c*128 + oc0];
    float4 wvb = *(const float4*)&wpt[c*128 + oc0 + 4];
    float4 ha  = *(const float4*)&ht[c*132 + px0];
    float4 hb4 = *(const float4*)&ht[c*132 + px0 + 4];
    float wvv[8] = {wva.x,wva.y,wva.z,wva.w,wvb.x,wvb.y,wvb.z,wvb.w};
    float hvv[8] = {ha.x,ha.y,ha.z,ha.w,hb4.x,hb4.y,hb4.z,hb4.w};
    #pragma unroll
    for (int o = 0; o < 8; o++)
      #pragma unroll
      for (int p = 0; p < 8; p++)
        acc[o][p] += wvv[o]*hvv[p];
  }

  float* ob = out + (b*128 + oc0)*HWc + h*Wc + px0;
  #pragma unroll
  for (int o = 0; o < 8; o++) {
    *(float4*)&ob[o*HWc]     = make_float4(acc[o][0],acc[o][1],acc[o][2],acc[o][3]);
    *(float4*)&ob[o*HWc + 4] = make_float4(acc[o][4],acc[o][5],acc[o][6],acc[o][7]);
  }
}

// ---------------------------------------------------------------------------
extern "C" void kernel_launch(void* const* d_in, const int* in_sizes, int n_in,
                              void* d_out, int out_size)
{
  const float* x   = (const float*)d_in[0];
  const float* w1  = (const float*)d_in[1];
  const float* b1  = (const float*)d_in[2];
  const float* a1  = (const float*)d_in[3];
  const float* wr  = (const float*)d_in[4];
  const float* br  = (const float*)d_in[5];
  const float* ws  = (const float*)d_in[6];
  const float* bs  = (const float*)d_in[7];
  const float* a2  = (const float*)d_in[8];
  const float* w2  = (const float*)d_in[9];
  const float* b2  = (const float*)d_in[10];
  const float* wa  = (const float*)d_in[11];
  const float* ba  = (const float*)d_in[12];
  const float* wp1 = (const float*)d_in[13];
  const float* bp1 = (const float*)d_in[14];
  const float* ap  = (const float*)d_in[15];
  const float* wp2 = (const float*)d_in[16];
  const float* bp2 = (const float*)d_in[17];
  float* out = (float*)d_out;

  const int s1 = 27136 * 4;   // k_front
  const int s2 = 28036 * 4;   // k_inv
  const int s3 = 19584 * 4;   // k_psec1
  const int s4 = 27090 * 4;   // k_final

  cudaFuncSetAttribute(k_front, cudaFuncAttributeMaxDynamicSharedMemorySize, s1);
  cudaFuncSetAttribute(k_inv,   cudaFuncAttributeMaxDynamicSharedMemorySize, s2);
  cudaFuncSetAttribute(k_psec1, cudaFuncAttributeMaxDynamicSharedMemorySize, s3);
  cudaFuncSetAttribute(k_final, cudaFuncAttributeMaxDynamicSharedMemorySize, s4);

  k_front<<<256, 256, s1>>>(x, w1, b1, a1, wr, br);
  k_inv  <<<dim3(4, 64, 2), 256, s2>>>(ws, bs, a2);
  k_psec1<<<dim3(8, 8, 2),  256, s3>>>(wp1, bp1, ap);
  k_final<<<256, 256, s4>>>(w2, b2, wa, ba, wp2, bp2, out);
}